// round 7
// baseline (speedup 1.0000x reference)
#include <cuda_runtime.h>

#define N_NODES 50000
#define E_EDGES 800000
#define F_INN   512
#define HIDD    128

#define NBLOCKS 592      // 148 SMs x 4 co-resident blocks (guaranteed by launch bounds)
#define NTHREADS 256
#define EPT 6            // 592*256*6 = 909312 >= E_EDGES

// ---------------- scratch (no allocs allowed) ----------------
__device__ float    g_u1[F_INN];       // gcn_w @ w1
__device__ float    g_u2[F_INN];       // gcn_w @ w2
__device__ float    g_beta;            // gcn_b.(w1+w2) + mlp_b
__device__ float    g_p1[N_NODES];     // feat[n].u1
__device__ float    g_p2[N_NODES];     // feat[n].u2
__device__ float    g_a[N_NODES];      // segment scatter of v*p1[col]
__device__ float    g_c[N_NODES];      // segment scatter of v*p2[col]
__device__ float    g_s[N_NODES];      // per-row sum of exp
__device__ unsigned g_bar;             // grid barrier counter (monotonic per launch)

// Per-block index-dtype detection (16 leading int64 words, L2-cached).
__device__ __forceinline__ int detect_is64(const void* idx) {
    const long long* p = (const long long*)idx;
    int is64 = 1;
#pragma unroll
    for (int i = 0; i < 16; i++) {
        long long v = p[i];
        if (v < 0 || v >= N_NODES) { is64 = 0; break; }
    }
    return is64;
}

// Software grid barrier: all NBLOCKS are co-resident (launch bounds), so
// spin-wait cannot deadlock. Monotonic target per phase; g_bar reset by a
// tiny kernel at the start of every launch.
__device__ __forceinline__ void gsync(unsigned target) {
    __syncthreads();
    if (threadIdx.x == 0) {
        __threadfence();
        atomicAdd(&g_bar, 1u);
        while (atomicAdd(&g_bar, 0u) < target) __nanosleep(64);
    }
    __syncthreads();
    __threadfence();
}

__global__ void reset_kernel() { g_bar = 0u; }

// ---------------- persistent fused kernel ----------------
__global__ void __launch_bounds__(NTHREADS, 4)
fused_kernel(const float* __restrict__ feat,
             const void*  __restrict__ idx,
             const float* __restrict__ vals,
             const float* __restrict__ gcn_w,
             const float* __restrict__ gcn_b,
             const float* __restrict__ mlp_w,
             const float* __restrict__ mlp_b,
             float* __restrict__ out) {
    const int tid = threadIdx.x;
    const int b   = blockIdx.x;
    const unsigned nb = gridDim.x;

    // ===== Phase 0: u1/u2, beta, zero a/c/s =====
    if (b < 2) {
        int k = b * NTHREADS + tid;               // 0..511
        const float* wrow = gcn_w + (size_t)k * HIDD;
        float s1 = 0.f, s2 = 0.f;
#pragma unroll 8
        for (int j = 0; j < HIDD; j++) {
            float w = wrow[j];
            s1 += w * mlp_w[j];
            s2 += w * mlp_w[HIDD + j];
        }
        g_u1[k] = s1;
        g_u2[k] = s2;
    } else if (b == 2 && tid < 32) {
        float s = 0.f;
        for (int j = tid; j < HIDD; j += 32)
            s += gcn_b[j] * (mlp_w[j] + mlp_w[HIDD + j]);
#pragma unroll
        for (int o = 16; o > 0; o >>= 1) s += __shfl_xor_sync(0xFFFFFFFFu, s, o);
        if (tid == 0) g_beta = s + mlp_b[0];
    }
    for (int i = b * NTHREADS + tid; i < N_NODES; i += nb * NTHREADS) {
        g_a[i] = 0.f; g_c[i] = 0.f; g_s[i] = 0.f;
    }
    gsync(1 * nb);

    // ===== Phase 1: p1/p2 (warp per node, grid-stride) =====
    {
        __shared__ float su1[F_INN];
        __shared__ float su2[F_INN];
        for (int i = tid; i < F_INN; i += NTHREADS) {
            su1[i] = g_u1[i];
            su2[i] = g_u2[i];
        }
        __syncthreads();

        int lane = tid & 31;
        for (int n = b * 8 + (tid >> 5); n < N_NODES; n += nb * 8) {
            const float* frow = feat + (size_t)n * F_INN;
            float s1 = 0.f, s2 = 0.f;
#pragma unroll
            for (int ch = 0; ch < 4; ch++) {
                int o = ch * 128 + lane * 4;
                float4 f = *(const float4*)(frow + o);
                s1 += f.x * su1[o] + f.y * su1[o + 1] + f.z * su1[o + 2] + f.w * su1[o + 3];
                s2 += f.x * su2[o] + f.y * su2[o + 1] + f.z * su2[o + 2] + f.w * su2[o + 3];
            }
#pragma unroll
            for (int o = 16; o > 0; o >>= 1) {
                s1 += __shfl_xor_sync(0xFFFFFFFFu, s1, o);
                s2 += __shfl_xor_sync(0xFFFFFFFFu, s2, o);
            }
            if (lane == 0) { g_p1[n] = s1; g_p2[n] = s2; }
        }
    }
    gsync(2 * nb);

    // ===== Phase 2: load edges ONCE into registers; scatter a/c =====
    int   er[EPT], ec[EPT];
    float ev[EPT], ex[EPT];
    const int base = b * NTHREADS * EPT + tid;
    {
        const int is64 = detect_is64(idx);
#pragma unroll
        for (int i = 0; i < EPT; i++) {
            int e = base + i * NTHREADS;
            if (e < E_EDGES) {
                if (is64) {
                    const long long* p = (const long long*)idx;
                    er[i] = (int)p[e];
                    ec[i] = (int)p[E_EDGES + e];
                } else {
                    const int* p = (const int*)idx;
                    er[i] = p[e];
                    ec[i] = p[E_EDGES + e];
                }
                ev[i] = vals[e];
            } else {
                er[i] = -1; ec[i] = 0; ev[i] = 0.f;
            }
        }
#pragma unroll
        for (int i = 0; i < EPT; i++) {
            if (er[i] >= 0) {
                atomicAdd(&g_a[er[i]], ev[i] * g_p1[ec[i]]);
                atomicAdd(&g_c[er[i]], ev[i] * g_p2[ec[i]]);
            }
        }
    }
    gsync(3 * nb);

    // ===== Phase 3: ex = exp(a[r]+c[c]+beta); s[r] += ex =====
    {
        float beta = g_beta;
#pragma unroll
        for (int i = 0; i < EPT; i++)
            ex[i] = (er[i] >= 0) ? expf(g_a[er[i]] + g_c[ec[i]] + beta) : 0.f;
#pragma unroll
        for (int i = 0; i < EPT; i++)
            if (er[i] >= 0) atomicAdd(&g_s[er[i]], ex[i]);
    }
    gsync(4 * nb);

    // ===== Phase 4: out = v + ex / s[r] =====
#pragma unroll
    for (int i = 0; i < EPT; i++) {
        int e = base + i * NTHREADS;
        if (er[i] >= 0) out[e] = ev[i] + ex[i] / g_s[er[i]];
    }
}

// ---------------- launch ----------------
extern "C" void kernel_launch(void* const* d_in, const int* in_sizes, int n_in,
                              void* d_out, int out_size) {
    const float* v_vals = (const float*)d_in[0];
    const float* feat   = (const float*)d_in[1];
    const void*  idx    = d_in[2];
    const float* gcn_w  = (const float*)d_in[n_in - 4];   // 512*128
    const float* gcn_b  = (const float*)d_in[n_in - 3];   // 128
    const float* mlp_w  = (const float*)d_in[n_in - 2];   // 256
    const float* mlp_b  = (const float*)d_in[n_in - 1];   // 1
    float*       out    = (float*)d_out;

    reset_kernel<<<1, 1>>>();
    fused_kernel<<<NBLOCKS, NTHREADS>>>(feat, idx, v_vals,
                                        gcn_w, gcn_b, mlp_w, mlp_b, out);
}

// round 8
// speedup vs baseline: 1.3249x; 1.3249x over previous
#include <cuda_runtime.h>

#define N_NODES 50000
#define E_EDGES 800000
#define F_INN   512
#define HIDD    128

// ---------------- scratch (no allocs allowed) ----------------
// Softmax cancellation: temp[e] = emb[row].w1 + emb[col].w2 + b, softmaxed
// within row groups. The emb[row].w1 + b part is constant per group and
// cancels. Only c[n] = emb[n].w2 (sans constant bias, which also cancels)
// matters: c[n] = sum_{e:row=n} v_e * (feat[col_e] . (gcn_w @ w2)).
__device__ float g_u2[F_INN];       // gcn_w @ w2
__device__ float g_p2[N_NODES];     // feat[n] . u2
__device__ float g_c[N_NODES];      // segment scatter of v*p2[col]
__device__ float g_s[N_NODES];      // per-row sum of exp(c[col])
__device__ float g_t[E_EDGES];      // per-edge exp (sequential reuse)
__device__ int2  g_rc[E_EDGES];     // packed (row, col)

// Per-block index-dtype detection (16 leading int64 words, L2-cached).
__device__ __forceinline__ int detect_is64(const void* idx) {
    const long long* p = (const long long*)idx;
    int is64 = 1;
#pragma unroll
    for (int i = 0; i < 16; i++) {
        long long v = p[i];
        if (v < 0 || v >= N_NODES) { is64 = 0; break; }
    }
    return is64;
}

// ---------------- K1: setup — u2, zero c/s ----------------
// blockIdx 0..1 : u2 (512 rows of gcn_w, 128-dot each)
// blockIdx 2..  : zero-init c, s
__global__ __launch_bounds__(256) void setup_kernel(const float* __restrict__ gcn_w,
                                                    const float* __restrict__ mlp_w) {
    int b = blockIdx.x;
    if (b < 2) {
        int k = b * 256 + threadIdx.x;           // 0..511
        const float* wrow = gcn_w + (size_t)k * HIDD;
        float s2 = 0.f;
#pragma unroll 8
        for (int j = 0; j < HIDD; j++)
            s2 += wrow[j] * mlp_w[HIDD + j];
        g_u2[k] = s2;
    } else {
        int i = (b - 2) * 256 + threadIdx.x;
        if (i < N_NODES) { g_c[i] = 0.f; g_s[i] = 0.f; }
    }
}

// ---------------- K2: p2[n] = feat[n] . u2 (warp per node) ----------------
__global__ __launch_bounds__(256) void p_kernel(const float* __restrict__ feat) {
    __shared__ float su2[F_INN];
    for (int i = threadIdx.x; i < F_INN; i += 256)
        su2[i] = g_u2[i];
    __syncthreads();

    int n = blockIdx.x * 8 + (threadIdx.x >> 5);
    if (n >= N_NODES) return;
    int lane = threadIdx.x & 31;
    const float* frow = feat + (size_t)n * F_INN;
    float s2 = 0.f;
#pragma unroll
    for (int ch = 0; ch < 4; ch++) {
        int o = ch * 128 + lane * 4;
        float4 f = *(const float4*)(frow + o);
        s2 += f.x * su2[o] + f.y * su2[o + 1] + f.z * su2[o + 2] + f.w * su2[o + 3];
    }
#pragma unroll
    for (int o = 16; o > 0; o >>= 1)
        s2 += __shfl_xor_sync(0xFFFFFFFFu, s2, o);
    if (lane == 0) g_p2[n] = s2;
}

// ---------------- K3: convert idx, pack rc, c[r] += v*p2[c] ----------------
__global__ void scatter_kernel(const void* __restrict__ idx,
                               const float* __restrict__ vals) {
    int e = blockIdx.x * blockDim.x + threadIdx.x;
    if (e >= E_EDGES) return;
    int r, c;
    if (detect_is64(idx)) {
        const long long* p = (const long long*)idx;
        r = (int)p[e];
        c = (int)p[E_EDGES + e];
    } else {
        const int* p = (const int*)idx;
        r = p[e];
        c = p[E_EDGES + e];
    }
    g_rc[e] = make_int2(r, c);
    atomicAdd(&g_c[r], vals[e] * g_p2[c]);
}

// ---------------- K4: ex = exp(c[col]); t[e] = ex; s[row] += ex ----------------
__global__ void sumexp_kernel() {
    int e = blockIdx.x * blockDim.x + threadIdx.x;
    if (e >= E_EDGES) return;
    int2 rc = g_rc[e];
    float ex = expf(g_c[rc.y]);
    g_t[e] = ex;
    atomicAdd(&g_s[rc.x], ex);
}

// ---------------- K5: out = v + t[e]/s[row] ----------------
__global__ void out_kernel(const float* __restrict__ vals,
                           float* __restrict__ out) {
    int e = blockIdx.x * blockDim.x + threadIdx.x;
    if (e >= E_EDGES) return;
    int r = g_rc[e].x;
    out[e] = vals[e] + g_t[e] / g_s[r];
}

// ---------------- launch ----------------
extern "C" void kernel_launch(void* const* d_in, const int* in_sizes, int n_in,
                              void* d_out, int out_size) {
    const float* v_vals = (const float*)d_in[0];
    const float* feat   = (const float*)d_in[1];
    const void*  idx    = d_in[2];
    const float* gcn_w  = (const float*)d_in[n_in - 4];   // 512*128
    const float* mlp_w  = (const float*)d_in[n_in - 2];   // 256
    float*       out    = (float*)d_out;

    int setup_blocks = 2 + (N_NODES + 255) / 256;
    setup_kernel<<<setup_blocks, 256>>>(gcn_w, mlp_w);

    p_kernel<<<(N_NODES + 7) / 8, 256>>>(feat);

    int edge_blocks = (E_EDGES + 255) / 256;
    scatter_kernel<<<edge_blocks, 256>>>(idx, v_vals);
    sumexp_kernel<<<edge_blocks, 256>>>();
    out_kernel<<<edge_blocks, 256>>>(v_vals, out);
}

// round 9
// speedup vs baseline: 1.3776x; 1.0398x over previous
#include <cuda_runtime.h>

#define N_NODES 50000
#define E_EDGES 800000
#define F_INN   512
#define HIDD    128

// ---------------- scratch (no allocs allowed) ----------------
// Softmax cancellation: temp[e] = emb[row].w1 + emb[col].w2 + b softmaxed
// within row groups -> the emb[row].w1 + b part cancels. Only
// c[n] = sum_{e:row=n} v_e * (feat[col_e] . (gcn_w @ w2)) matters.
__device__ float g_u2[F_INN];       // gcn_w @ w2
__device__ float g_p2[N_NODES];     // feat[n] . u2
__device__ float g_c[N_NODES];      // segment scatter of v*p2[col]
__device__ float g_s[N_NODES];      // per-row sum of exp(c[col])
__device__ float g_t[E_EDGES];      // per-edge exp (sequential reuse)
__device__ int2  g_rc[E_EDGES];     // packed (row, col)

// Per-block index-dtype detection (16 leading int64 words, L2-cached).
__device__ __forceinline__ int detect_is64(const void* idx) {
    const long long* p = (const long long*)idx;
    int is64 = 1;
#pragma unroll
    for (int i = 0; i < 16; i++) {
        long long v = p[i];
        if (v < 0 || v >= N_NODES) { is64 = 0; break; }
    }
    return is64;
}

// ---------------- K1: setup — u2, zero c/s ----------------
__global__ __launch_bounds__(256) void setup_kernel(const float* __restrict__ gcn_w,
                                                    const float* __restrict__ mlp_w) {
    int b = blockIdx.x;
    if (b < 2) {
        int k = b * 256 + threadIdx.x;           // 0..511
        const float* wrow = gcn_w + (size_t)k * HIDD;
        float s2 = 0.f;
#pragma unroll 8
        for (int j = 0; j < HIDD; j++)
            s2 += wrow[j] * mlp_w[HIDD + j];
        g_u2[k] = s2;
    } else {
        int i = (b - 2) * 256 + threadIdx.x;
        if (i < N_NODES) { g_c[i] = 0.f; g_s[i] = 0.f; }
    }
}

// ---------------- K2: p2[n] = feat[n] . u2 — 2 nodes/warp, prefetch + PDL ----------------
__global__ __launch_bounds__(256) void p_kernel(const float* __restrict__ feat) {
    __shared__ float su2[F_INN];
    const int w    = threadIdx.x >> 5;
    const int lane = threadIdx.x & 31;
    const int n0   = blockIdx.x * 16 + w * 2;    // 3125*16 == 50000, no bounds needed
    const float* r0 = feat + (size_t)n0 * F_INN;
    const float* r1 = r0 + F_INN;

    // Prefetch both rows (inputs, independent of setup) BEFORE the dependency sync.
    float4 f0[4], f1[4];
#pragma unroll
    for (int ch = 0; ch < 4; ch++) {
        int o = ch * 128 + lane * 4;
        f0[ch] = *(const float4*)(r0 + o);
        f1[ch] = *(const float4*)(r1 + o);
    }

    cudaGridDependencySynchronize();             // wait for setup's u2

    for (int i = threadIdx.x; i < F_INN; i += 256)
        su2[i] = g_u2[i];
    __syncthreads();

    float s0 = 0.f, s1 = 0.f;
#pragma unroll
    for (int ch = 0; ch < 4; ch++) {
        int o = ch * 128 + lane * 4;
        s0 += f0[ch].x * su2[o] + f0[ch].y * su2[o + 1] + f0[ch].z * su2[o + 2] + f0[ch].w * su2[o + 3];
        s1 += f1[ch].x * su2[o] + f1[ch].y * su2[o + 1] + f1[ch].z * su2[o + 2] + f1[ch].w * su2[o + 3];
    }
#pragma unroll
    for (int o = 16; o > 0; o >>= 1) {
        s0 += __shfl_xor_sync(0xFFFFFFFFu, s0, o);
        s1 += __shfl_xor_sync(0xFFFFFFFFu, s1, o);
    }
    if (lane == 0) { g_p2[n0] = s0; g_p2[n0 + 1] = s1; }
}

// ---------------- K3: decode idx, pack rc, c[r] += v*p2[c] ----------------
__global__ void scatter_kernel(const void* __restrict__ idx,
                               const float* __restrict__ vals) {
    int e = blockIdx.x * blockDim.x + threadIdx.x;
    if (e >= E_EDGES) return;
    // Inputs + scratch write are independent of p_kernel: do before sync.
    int r, c;
    if (detect_is64(idx)) {
        const long long* p = (const long long*)idx;
        r = (int)p[e];
        c = (int)p[E_EDGES + e];
    } else {
        const int* p = (const int*)idx;
        r = p[e];
        c = p[E_EDGES + e];
    }
    float v = vals[e];
    g_rc[e] = make_int2(r, c);

    cudaGridDependencySynchronize();             // wait for p2
    atomicAdd(&g_c[r], v * g_p2[c]);
}

// ---------------- K4: ex = exp(c[col]); t[e] = ex; s[row] += ex ----------------
__global__ void sumexp_kernel() {
    int e = blockIdx.x * blockDim.x + threadIdx.x;
    cudaGridDependencySynchronize();             // wait for scatter (rc + c)
    if (e >= E_EDGES) return;
    int2 rc = g_rc[e];
    float ex = expf(g_c[rc.y]);
    g_t[e] = ex;
    atomicAdd(&g_s[rc.x], ex);
}

// ---------------- K5: out = v + t[e]/s[row] ----------------
__global__ void out_kernel(const float* __restrict__ vals,
                           float* __restrict__ out) {
    int e = blockIdx.x * blockDim.x + threadIdx.x;
    float v = (e < E_EDGES) ? vals[e] : 0.f;     // input prefetch before sync
    cudaGridDependencySynchronize();             // wait for sumexp (t + s)
    if (e >= E_EDGES) return;
    int r = g_rc[e].x;
    out[e] = v + __fdividef(g_t[e], g_s[r]);
}

// ---------------- launch helpers ----------------
template <typename... Args>
static void launch_pdl(void (*kern)(Args...), int grid, int block, Args... args) {
    cudaLaunchConfig_t cfg = {};
    cfg.gridDim  = dim3(grid);
    cfg.blockDim = dim3(block);
    cudaLaunchAttribute at[1];
    at[0].id = cudaLaunchAttributeProgrammaticStreamSerialization;
    at[0].val.programmaticStreamSerializationAllowed = 1;
    cfg.attrs = at;
    cfg.numAttrs = 1;
    cudaLaunchKernelEx(&cfg, kern, args...);
}

extern "C" void kernel_launch(void* const* d_in, const int* in_sizes, int n_in,
                              void* d_out, int out_size) {
    const float* v_vals = (const float*)d_in[0];
    const float* feat   = (const float*)d_in[1];
    const void*  idx    = d_in[2];
    const float* gcn_w  = (const float*)d_in[n_in - 4];   // 512*128
    const float* mlp_w  = (const float*)d_in[n_in - 2];   // 256
    float*       out    = (float*)d_out;

    int setup_blocks = 2 + (N_NODES + 255) / 256;
    setup_kernel<<<setup_blocks, 256>>>(gcn_w, mlp_w);

    launch_pdl(p_kernel, N_NODES / 16, 256, feat);

    int edge_blocks = (E_EDGES + 255) / 256;
    launch_pdl(scatter_kernel, edge_blocks, 256, idx, v_vals);
    launch_pdl(sumexp_kernel, edge_blocks, 256);
    launch_pdl(out_kernel, edge_blocks, 256, v_vals, out);
}